// round 9
// baseline (speedup 1.0000x reference)
#include <cuda_runtime.h>
#include <cstdint>

#define NB 16384
#define NT 1024
#define HH 64
#define TPB 64                // 2 warps = k-half pair; 4 elements per block
#define GRID (NB / 4)         // 4096 blocks

#define L2E2 2.8853900817779268f   // 2*log2(e), folded into W1/b1/W2/b2

typedef unsigned long long u64;

static __device__ __forceinline__ u64 fma2(u64 a, u64 b, u64 c) {
    u64 d;
    asm("fma.rn.f32x2 %0, %1, %2, %3;" : "=l"(d) : "l"(a), "l"(b), "l"(c));
    return d;
}
static __device__ __forceinline__ u64 pk(float a, float b) {
    u64 d;
    asm("mov.b64 %0, {%1, %2};" : "=l"(d) : "f"(a), "f"(b));
    return d;
}
static __device__ __forceinline__ u64 dup2(float a) {
    u64 d;
    asm("mov.b64 %0, {%1, %1};" : "=l"(d) : "f"(a));
    return d;
}
static __device__ __forceinline__ void upk(u64 v, float& a, float& b) {
    asm("mov.b64 {%0, %1}, %2;" : "=f"(a), "=f"(b) : "l"(v));
}
static __device__ __forceinline__ u64 shfl_xor64(u64 v, int m) {
    uint32_t lo = (uint32_t)v, hi = (uint32_t)(v >> 32);
    lo = __shfl_xor_sync(0xffffffffu, lo, m);
    hi = __shfl_xor_sync(0xffffffffu, hi, m);
    return ((u64)hi << 32) | lo;
}
// tanh with prescaled arg a = 2*log2(e)*x: tanh(x) = 1 - 2/(2^a + 1).
// Validated at rel_err ~3e-7 over 1023 steps (rounds 1-8).
static __device__ __forceinline__ float tanh_pre(float a) {
    float e, r;
    asm("ex2.approx.f32 %0, %1;" : "=f"(e) : "f"(a));
    asm("rcp.approx.f32 %0, %1;" : "=f"(r) : "f"(e + 1.0f));
    return fmaf(-2.0f, r, 1.0f);
}

__device__ __constant__ float cA[5][5] = {
    {(float)(1.0 / 5.0), 0.f, 0.f, 0.f, 0.f},
    {(float)(3.0 / 40.0), (float)(9.0 / 40.0), 0.f, 0.f, 0.f},
    {(float)(44.0 / 45.0), (float)(-56.0 / 15.0), (float)(32.0 / 9.0), 0.f, 0.f},
    {(float)(19372.0 / 6561.0), (float)(-25360.0 / 2187.0),
     (float)(64448.0 / 6561.0), (float)(-212.0 / 729.0), 0.f},
    {(float)(9017.0 / 3168.0), (float)(-355.0 / 33.0),
     (float)(46732.0 / 5247.0), (float)(49.0 / 176.0),
     (float)(-5103.0 / 18656.0)},
};

__global__ void __launch_bounds__(TPB, 6)
ode_kernel(const float* __restrict__ y0, const float* __restrict__ ts,
           const float* __restrict__ W1, const float* __restrict__ b1,
           const float* __restrict__ W2, const float* __restrict__ b2,
           const float* __restrict__ W3, const float* __restrict__ b3,
           float* __restrict__ out) {
    // hb stride 72 floats: layer-1 STS octets hit 8 distinct bank-chunks.
    __shared__ __align__(16) float hb[4][72];     // [m][k] layer-1 activations
    __shared__ __align__(16) float pre[2][4][64]; // [warp][m][j] k-half preacts
    __shared__ float2 fxy[6][2][4];               // [st][warp][m] f partials
    __shared__ float dts[NT];

    const int tid = threadIdx.x;
    for (int i = tid; i < NT - 1; i += TPB) dts[i] = ts[i + 1] - ts[i];

    const int lane = tid & 31;
    const int w = tid >> 5;          // k-half: k in [32w, 32w+32)
    const int o = lane & 7;          // j-octet: j in [8o, 8o+8)
    const int kq = lane >> 3;        // k-subrange: [32w+8kq, +8)
    const int m1 = tid & 3;          // layer-1 / state element
    const int kc = tid >> 2;         // layer-1 k-quad: units 4kc..4kc+3
    const int mD = lane >> 3;        // phase-D element
    const int jq = lane & 7;         // phase-D j-quad
    const int jD = 32 * w + 4 * jq;  // phase-D j base
    const int e0 = blockIdx.x * 4;

    // ---- W2 block into registers: 8 j (4 pairs) x 8 k, prescaled ----
    u64 w2r[4][8];
#pragma unroll
    for (int jp = 0; jp < 4; jp++) {
        const int j = 8 * o + 2 * jp;
#pragma unroll
        for (int kk = 0; kk < 8; kk++) {
            const int kg = 32 * w + 8 * kq + kk;
            w2r[jp][kk] = pk(W2[j * HH + kg] * L2E2,
                             W2[(j + 1) * HH + kg] * L2E2);
        }
    }
    // ---- layer-1 weights for this thread's 4 units ----
    float w1xr[4], w1yr[4], b1r[4];
#pragma unroll
    for (int i = 0; i < 4; i++) {
        const int u = 4 * kc + i;
        w1xr[i] = W1[2 * u] * L2E2;
        w1yr[i] = W1[2 * u + 1] * L2E2;
        b1r[i] = b1[u] * L2E2;
    }
    // ---- phase-D constants for this lane's 4 j's ----
    float b2r[4];
    u64 w3r[4];
#pragma unroll
    for (int i = 0; i < 4; i++) {
        b2r[i] = b2[jD + i] * L2E2;
        w3r[i] = pk(W3[jD + i], W3[HH + jD + i]);
    }
    const float b3x = b3[0], b3y = b3[1];
    const u64 one2 = dup2(1.0f);

    const float2 yv = ((const float2*)y0)[e0 + m1];
    float yx = yv.x, yy = yv.y;
    float2* o2 = (float2*)out;
    if (tid < 4) o2[e0 + m1] = yv;   // SaveAt includes the initial state
    __syncthreads();                 // dts ready

    const float B1 = (float)(35.0 / 384.0);
    const float B3 = (float)(500.0 / 1113.0);
    const float B4 = (float)(125.0 / 192.0);
    const float B5 = (float)(-2187.0 / 6784.0);
    const float B6 = (float)(11.0 / 84.0);

    for (int t = 0; t < NT - 1; t++) {
        const float dtv = dts[t];
        float kx6[6], ky6[6];

#pragma unroll 1
        for (int st = 0; st < 6; st++) {
            // ---- stage input for this thread's element m1 ----
            float sx, sy;
            if (st == 0) {
                sx = yx; sy = yy;
            } else {
                float ax = 0.f, ay = 0.f;
                for (int i = 0; i < st; i++) {
                    const float a = cA[st - 1][i];
                    ax = fmaf(a, kx6[i], ax);
                    ay = fmaf(a, ky6[i], ay);
                }
                sx = fmaf(dtv, ax, yx);
                sy = fmaf(dtv, ay, yy);
            }

            // ---- layer 1: 4 units (= k indices 4kc..4kc+3) for element m1 ----
            {
                float4 hv;
                hv.x = tanh_pre(fmaf(sx, w1xr[0], fmaf(sy, w1yr[0], b1r[0])));
                hv.y = tanh_pre(fmaf(sx, w1xr[1], fmaf(sy, w1yr[1], b1r[1])));
                hv.z = tanh_pre(fmaf(sx, w1xr[2], fmaf(sy, w1yr[2], b1r[2])));
                hv.w = tanh_pre(fmaf(sx, w1xr[3], fmaf(sy, w1yr[3], b1r[3])));
                *(float4*)&hb[m1][4 * kc] = hv;   // warp-local k range
            }
            __syncwarp();   // hb RAW (producer warp == consumer warp)

            // ---- layer 2: reg weights x smem h; acc[m][jpair] ----
            u64 acc[4][4];
#pragma unroll
            for (int m = 0; m < 4; m++)
#pragma unroll
                for (int jp = 0; jp < 4; jp++) acc[m][jp] = 0ull;

#pragma unroll
            for (int kp = 0; kp < 2; kp++) {
                float hlv[4][4];
#pragma unroll
                for (int m = 0; m < 4; m++)
                    *(float4*)&hlv[m][0] =
                        *(const float4*)&hb[m][32 * w + 8 * kq + 4 * kp];
#pragma unroll
                for (int i = 0; i < 4; i++) {
                    const int kk = 4 * kp + i;
#pragma unroll
                    for (int m = 0; m < 4; m++) {
                        const u64 hd = dup2(hlv[m][i]);
                        acc[m][0] = fma2(hd, w2r[0][kk], acc[m][0]);
                        acc[m][1] = fma2(hd, w2r[1][kk], acc[m][1]);
                        acc[m][2] = fma2(hd, w2r[2][kk], acc[m][2]);
                        acc[m][3] = fma2(hd, w2r[3][kk], acc[m][3]);
                    }
                }
            }

            // ---- split-butterfly reduce over the 4 kq lanes ----
            const int mp = kq & 1, jph = (kq >> 1) & 1;
            u64 keep[2][4];
#pragma unroll
            for (int r = 0; r < 2; r++)
#pragma unroll
                for (int jp = 0; jp < 4; jp++) {
                    const u64 d = mp ? acc[r][jp] : acc[2 + r][jp];      // give
                    const u64 k = mp ? acc[2 + r][jp] : acc[r][jp];      // keep
                    keep[r][jp] = fma2(one2, shfl_xor64(d, 8), k);
                }
            u64 f2[2][2];
#pragma unroll
            for (int r = 0; r < 2; r++)
#pragma unroll
                for (int p = 0; p < 2; p++) {
                    const u64 d = jph ? keep[r][p] : keep[r][2 + p];
                    const u64 k = jph ? keep[r][2 + p] : keep[r][p];
                    f2[r][p] = fma2(one2, shfl_xor64(d, 16), k);
                }
            // lane now holds k-half sums for m in {2mp, 2mp+1},
            // j in [8o+4jph, 8o+4jph+4)
#pragma unroll
            for (int r = 0; r < 2; r++)
#pragma unroll
                for (int p = 0; p < 2; p++)
                    *(u64*)&pre[w][2 * mp + r][8 * o + 4 * jph + 2 * p] = f2[r][p];
            __syncthreads();   // pre complete (both warps)

            // ---- phase D: layer-2 tanh + layer 3 for (mD, jD..jD+3) ----
            const float4 pA = *(const float4*)&pre[0][mD][jD];
            const float4 pB = *(const float4*)&pre[1][mD][jD];
            const float g0 = tanh_pre(pA.x + pB.x + b2r[0]);
            const float g1 = tanh_pre(pA.y + pB.y + b2r[1]);
            const float g2 = tanh_pre(pA.z + pB.z + b2r[2]);
            const float g3 = tanh_pre(pA.w + pB.w + b2r[3]);
            u64 accP = 0ull;
            accP = fma2(dup2(g0), w3r[0], accP);
            accP = fma2(dup2(g1), w3r[1], accP);
            accP = fma2(dup2(g2), w3r[2], accP);
            accP = fma2(dup2(g3), w3r[3], accP);
            accP = fma2(one2, shfl_xor64(accP, 1), accP);
            accP = fma2(one2, shfl_xor64(accP, 2), accP);
            accP = fma2(one2, shfl_xor64(accP, 4), accP);
            if (jq == 0) {
                float fx, fy;
                upk(accP, fx, fy);
                fxy[st][w][mD] = make_float2(fx, fy);
            }
            __syncthreads();   // fxy complete; also WAR for hb/pre next stage

            const float2 fa = fxy[st][0][m1];
            const float2 fb = fxy[st][1][m1];
            kx6[st] = fa.x + fb.x + b3x;
            ky6[st] = fa.y + fb.y + b3y;
        }

        // ---- combine and advance (element m1; identical across its lanes) ----
        float ax = B1 * kx6[0], ay = B1 * ky6[0];
        ax = fmaf(B3, kx6[2], ax); ay = fmaf(B3, ky6[2], ay);
        ax = fmaf(B4, kx6[3], ax); ay = fmaf(B4, ky6[3], ay);
        ax = fmaf(B5, kx6[4], ax); ay = fmaf(B5, ky6[4], ay);
        ax = fmaf(B6, kx6[5], ax); ay = fmaf(B6, ky6[5], ay);
        yx = fmaf(dtv, ax, yx);
        yy = fmaf(dtv, ay, yy);
        if (tid < 4)
            o2[(size_t)(t + 1) * NB + e0 + m1] = make_float2(yx, yy);
    }
}

extern "C" void kernel_launch(void* const* d_in, const int* in_sizes, int n_in,
                              void* d_out, int out_size) {
    const float* y0 = (const float*)d_in[0];
    const float* ts = (const float*)d_in[1];
    const float* W1 = (const float*)d_in[2];
    const float* b1 = (const float*)d_in[3];
    const float* W2 = (const float*)d_in[4];
    const float* b2 = (const float*)d_in[5];
    const float* W3 = (const float*)d_in[6];
    const float* b3 = (const float*)d_in[7];
    ode_kernel<<<GRID, TPB>>>(y0, ts, W1, b1, W2, b2, W3, b3, (float*)d_out);
}

// round 10
// speedup vs baseline: 1.0162x; 1.0162x over previous
#include <cuda_runtime.h>
#include <cstdint>

#define NB 16384
#define NT 1024
#define HH 64
#define TPB 64                // 2 warps; 4 elements per block
#define GRID (NB / 4)         // 4096 blocks -> 8192 warps

#define L2E2 2.8853900817779268f   // 2*log2(e), folded into W1/b1/W2/b2
// hb index: 16B gap between k-halves so kl=0/kl=1 LDS.128 hit disjoint banks
#define HIDX(k) ((k) + ((((k) >> 5)) << 2))

typedef unsigned long long u64;

static __device__ __forceinline__ u64 fma2(u64 a, u64 b, u64 c) {
    u64 d;
    asm("fma.rn.f32x2 %0, %1, %2, %3;" : "=l"(d) : "l"(a), "l"(b), "l"(c));
    return d;
}
static __device__ __forceinline__ u64 add2(u64 a, u64 b) {
    u64 d;
    asm("add.rn.f32x2 %0, %1, %2;" : "=l"(d) : "l"(a), "l"(b));
    return d;
}
static __device__ __forceinline__ u64 pk(float a, float b) {
    u64 d;
    asm("mov.b64 %0, {%1, %2};" : "=l"(d) : "f"(a), "f"(b));
    return d;
}
static __device__ __forceinline__ u64 dup2(float a) {
    u64 d;
    asm("mov.b64 %0, {%1, %1};" : "=l"(d) : "f"(a));
    return d;
}
static __device__ __forceinline__ void upk(u64 v, float& a, float& b) {
    asm("mov.b64 {%0, %1}, %2;" : "=f"(a), "=f"(b) : "l"(v));
}
static __device__ __forceinline__ u64 shfl_xor64(u64 v, int m) {
    uint32_t lo = (uint32_t)v, hi = (uint32_t)(v >> 32);
    lo = __shfl_xor_sync(0xffffffffu, lo, m);
    hi = __shfl_xor_sync(0xffffffffu, hi, m);
    return ((u64)hi << 32) | lo;
}
// tanh with prescaled arg a = 2*log2(e)*x: tanh(x) = 1 - 2/(2^a + 1).
// Validated at rel_err ~3e-7 over 1023 steps (rounds 1-9).
static __device__ __forceinline__ float tanh_pre(float a) {
    float e, r;
    asm("ex2.approx.f32 %0, %1;" : "=f"(e) : "f"(a));
    asm("rcp.approx.f32 %0, %1;" : "=f"(r) : "f"(e + 1.0f));
    return fmaf(-2.0f, r, 1.0f);
}

__device__ __constant__ float cA[5][5] = {
    {(float)(1.0 / 5.0), 0.f, 0.f, 0.f, 0.f},
    {(float)(3.0 / 40.0), (float)(9.0 / 40.0), 0.f, 0.f, 0.f},
    {(float)(44.0 / 45.0), (float)(-56.0 / 15.0), (float)(32.0 / 9.0), 0.f, 0.f},
    {(float)(19372.0 / 6561.0), (float)(-25360.0 / 2187.0),
     (float)(64448.0 / 6561.0), (float)(-212.0 / 729.0), 0.f},
    {(float)(9017.0 / 3168.0), (float)(-355.0 / 33.0),
     (float)(46732.0 / 5247.0), (float)(49.0 / 176.0),
     (float)(-5103.0 / 18656.0)},
};

__global__ void __launch_bounds__(TPB, 6)
ode_kernel(const float* __restrict__ y0, const float* __restrict__ ts,
           const float* __restrict__ W1, const float* __restrict__ b1,
           const float* __restrict__ W2, const float* __restrict__ b2,
           const float* __restrict__ W3, const float* __restrict__ b3,
           float* __restrict__ out) {
    __shared__ __align__(16) float hb[4][72];   // [m][HIDX(k)] activations
    __shared__ float2 fxy[6][2][4];             // [st][w][m] warp f-partials
    __shared__ float dts[NT];

    const int tid = threadIdx.x;
    for (int i = tid; i < NT - 1; i += TPB) dts[i] = ts[i + 1] - ts[i];

    const int lane = tid & 31;
    const int w = tid >> 5;          // warp's j-half: j in [32w, 32w+32)
    const int jl = lane & 15;        // j-pair lane: j0 = 32w + 2jl
    const int kl = lane >> 4;        // k-half within warp: k in [32kl, +32)
    const int j0 = 32 * w + 2 * jl;
    const int m1 = tid & 3;          // this thread's state element
    const int kc = tid >> 2;         // layer-1 unit quad: 4kc..4kc+3
    const int e0 = blockIdx.x * 4;

    // ---- W2 block into registers: 2 j x 16 k-pairs (k-parity packed) ----
    u64 w2r[2][16];
#pragma unroll
    for (int jp = 0; jp < 2; jp++) {
        const float4* row = (const float4*)(W2 + (j0 + jp) * HH + 32 * kl);
#pragma unroll
        for (int q = 0; q < 8; q++) {
            const float4 v = row[q];
            w2r[jp][2 * q]     = pk(v.x * L2E2, v.y * L2E2);
            w2r[jp][2 * q + 1] = pk(v.z * L2E2, v.w * L2E2);
        }
    }
    // ---- layer-1 weights for this thread's 4 units ----
    float w1xr[4], w1yr[4], b1r[4];
#pragma unroll
    for (int i = 0; i < 4; i++) {
        const int u = 4 * kc + i;
        w1xr[i] = W1[2 * u] * L2E2;
        w1yr[i] = W1[2 * u + 1] * L2E2;
        b1r[i] = b1[u] * L2E2;
    }
    // ---- phase-D constants for this lane's 2 j's ----
    float b2r[2];
    u64 w3r[2];
#pragma unroll
    for (int jp = 0; jp < 2; jp++) {
        b2r[jp] = b2[j0 + jp] * L2E2;
        w3r[jp] = pk(W3[j0 + jp], W3[HH + j0 + jp]);
    }
    const float b3x = b3[0], b3y = b3[1];

    const float2 yv = ((const float2*)y0)[e0 + m1];
    float yx = yv.x, yy = yv.y;
    float2* o2 = (float2*)out;
    if (tid < 4) o2[e0 + m1] = yv;   // SaveAt includes the initial state
    __syncthreads();                 // dts ready

    const float B1 = (float)(35.0 / 384.0);
    const float B3 = (float)(500.0 / 1113.0);
    const float B4 = (float)(125.0 / 192.0);
    const float B5 = (float)(-2187.0 / 6784.0);
    const float B6 = (float)(11.0 / 84.0);

    const int hoff = 36 * kl;        // HIDX(32*kl)

    for (int t = 0; t < NT - 1; t++) {
        const float dtv = dts[t];
        float kx6[6], ky6[6];

#pragma unroll 1
        for (int st = 0; st < 6; st++) {
            // ---- stage input for element m1 ----
            float sx, sy;
            if (st == 0) {
                sx = yx; sy = yy;
            } else {
                float ax = 0.f, ay = 0.f;
                for (int i = 0; i < st; i++) {
                    const float a = cA[st - 1][i];
                    ax = fmaf(a, kx6[i], ax);
                    ay = fmaf(a, ky6[i], ay);
                }
                sx = fmaf(dtv, ax, yx);
                sy = fmaf(dtv, ay, yy);
            }

            // ---- layer 1: 4 units (k = 4kc..4kc+3) for element m1 ----
            {
                float4 hv;
                hv.x = tanh_pre(fmaf(sx, w1xr[0], fmaf(sy, w1yr[0], b1r[0])));
                hv.y = tanh_pre(fmaf(sx, w1xr[1], fmaf(sy, w1yr[1], b1r[1])));
                hv.z = tanh_pre(fmaf(sx, w1xr[2], fmaf(sy, w1yr[2], b1r[2])));
                hv.w = tanh_pre(fmaf(sx, w1xr[3], fmaf(sy, w1yr[3], b1r[3])));
                *(float4*)&hb[m1][HIDX(4 * kc)] = hv;
            }
            __syncthreads();   // hb complete (cross-warp k coverage)

            // ---- layer 2: reg weights, natural-pair h, NO duplication ----
            u64 acc[4][2];
#pragma unroll
            for (int m = 0; m < 4; m++) { acc[m][0] = 0ull; acc[m][1] = 0ull; }

#pragma unroll
            for (int q = 0; q < 8; q++) {
                const u64 wa0 = w2r[0][2 * q], wa1 = w2r[0][2 * q + 1];
                const u64 wb0 = w2r[1][2 * q], wb1 = w2r[1][2 * q + 1];
#pragma unroll
                for (int m = 0; m < 4; m++) {
                    const float4 hvq = *(const float4*)&hb[m][hoff + 4 * q];
                    const u64 pA = ((const u64*)&hvq)[0];  // (h_even, h_odd)
                    const u64 pB = ((const u64*)&hvq)[1];
                    acc[m][0] = fma2(pA, wa0, acc[m][0]);
                    acc[m][1] = fma2(pA, wb0, acc[m][1]);
                    acc[m][0] = fma2(pB, wa1, acc[m][0]);
                    acc[m][1] = fma2(pB, wb1, acc[m][1]);
                }
            }

            // ---- reduce over the 2 kl lanes (split-butterfly, m-halved) ----
            u64 red[2][2];   // [r][jp], m = 2*kl + r
#pragma unroll
            for (int r = 0; r < 2; r++)
#pragma unroll
                for (int jp = 0; jp < 2; jp++) {
                    const u64 gv = kl ? acc[r][jp] : acc[2 + r][jp];
                    const u64 kv = kl ? acc[2 + r][jp] : acc[r][jp];
                    red[r][jp] = add2(kv, shfl_xor64(gv, 16));
                }

            // ---- phase D: hi+lo merge, bias, tanh, layer 3 ----
            u64 accP[2];
#pragma unroll
            for (int r = 0; r < 2; r++) {
                float l0, h0, l1, h1;
                upk(red[r][0], l0, h0);
                upk(red[r][1], l1, h1);
                const float g0 = tanh_pre(l0 + h0 + b2r[0]);
                const float g1 = tanh_pre(l1 + h1 + b2r[1]);
                accP[r] = fma2(dup2(g0), w3r[0], fma2(dup2(g1), w3r[1], 0ull));
            }

            // ---- reduce over 16 jl lanes (first round splits m) ----
            {
                const int p = jl & 1;
                const u64 gv = p ? accP[0] : accP[1];
                const u64 kv = p ? accP[1] : accP[0];
                u64 s = add2(kv, shfl_xor64(gv, 1));   // m = 2*kl + p
                s = add2(s, shfl_xor64(s, 2));
                s = add2(s, shfl_xor64(s, 4));
                s = add2(s, shfl_xor64(s, 8));
                if (jl < 2) {
                    float fx, fy;
                    upk(s, fx, fy);
                    fxy[st][w][2 * kl + jl] = make_float2(fx, fy);
                }
            }
            __syncthreads();   // fxy complete; WAR cover for hb next stage

            const float2 fa = fxy[st][0][m1];
            const float2 fb = fxy[st][1][m1];
            kx6[st] = fa.x + fb.x + b3x;
            ky6[st] = fa.y + fb.y + b3y;
        }

        // ---- combine and advance ----
        float ax = B1 * kx6[0], ay = B1 * ky6[0];
        ax = fmaf(B3, kx6[2], ax); ay = fmaf(B3, ky6[2], ay);
        ax = fmaf(B4, kx6[3], ax); ay = fmaf(B4, ky6[3], ay);
        ax = fmaf(B5, kx6[4], ax); ay = fmaf(B5, ky6[4], ay);
        ax = fmaf(B6, kx6[5], ax); ay = fmaf(B6, ky6[5], ay);
        yx = fmaf(dtv, ax, yx);
        yy = fmaf(dtv, ay, yy);
        if (tid < 4)
            o2[(size_t)(t + 1) * NB + e0 + m1] = make_float2(yx, yy);
    }
}

extern "C" void kernel_launch(void* const* d_in, const int* in_sizes, int n_in,
                              void* d_out, int out_size) {
    const float* y0 = (const float*)d_in[0];
    const float* ts = (const float*)d_in[1];
    const float* W1 = (const float*)d_in[2];
    const float* b1 = (const float*)d_in[3];
    const float* W2 = (const float*)d_in[4];
    const float* b2 = (const float*)d_in[5];
    const float* W3 = (const float*)d_in[6];
    const float* b3 = (const float*)d_in[7];
    ode_kernel<<<GRID, TPB>>>(y0, ts, W1, b1, W2, b2, W3, b3, (float*)d_out);
}